// round 2
// baseline (speedup 1.0000x reference)
#include <cuda_runtime.h>
#include <cuda_bf16.h>
#include <cstdint>

#define Bb 4
#define HWD 1024   // 32*32 flattened outer (and inner) spatial dims
#define EPSF 1e-5f

// ---------------- scratch (device globals; no allocation allowed) ----------------
__device__ float g_mm  [(size_t)Bb*HWD*HWD];
__device__ float g_mmT [(size_t)Bb*HWD*HWD];
__device__ float g_P   [(size_t)Bb*10*HWD*HWD];
__device__ float g_PT  [(size_t)Bb*10*HWD*HWD];
__device__ float g_A   [(size_t)Bb*10*HWD*HWD];
__device__ float g_Bf  [(size_t)Bb*10*HWD*HWD];
__device__ float g_y1  [(size_t)Bb*HWD*HWD];
__device__ float g_z   [(size_t)Bb*HWD*HWD];
__device__ float g_attn[(size_t)Bb*HWD*HWD];
__device__ float    g_amax [Bb*HWD];
__device__ unsigned g_bmaxu[Bb*HWD];

// ---------------- helpers ----------------
__device__ __forceinline__ unsigned enc_f(float f) {
    unsigned u = __float_as_uint(f);
    return (u & 0x80000000u) ? ~u : (u | 0x80000000u);
}
__device__ __forceinline__ float dec_f(unsigned u) {
    return __uint_as_float((u & 0x80000000u) ? (u & 0x7fffffffu) : ~u);
}

// ---------------- max reductions ----------------
__global__ void initb_kernel() {
    int i = blockIdx.x * blockDim.x + threadIdx.x;
    if (i < Bb * HWD) g_bmaxu[i] = 0u;
}

// row max over inner dim (a_max). p2 optional (cf = y1+z path).
__global__ void rowmax_kernel(const float* __restrict__ p1, const float* __restrict__ p2,
                              float* __restrict__ om) {
    int row = blockIdx.x;                 // b*HWD + o
    size_t base = (size_t)row * HWD;
    int tid = threadIdx.x;
    float m = -3.4e38f;
    if (p2) {
        for (int j = tid; j < HWD; j += 256) m = fmaxf(m, p1[base + j] + p2[base + j]);
    } else {
        for (int j = tid; j < HWD; j += 256) m = fmaxf(m, p1[base + j]);
    }
    __shared__ float red[256];
    red[tid] = m; __syncthreads();
    for (int s = 128; s > 0; s >>= 1) {
        if (tid < s) red[tid] = fmaxf(red[tid], red[tid + s]);
        __syncthreads();
    }
    if (tid == 0) om[row] = red[0];
}

// column max over outer dim (b_max), atomicMax on order-preserving uint.
__global__ void colmax_kernel(const float* __restrict__ p1, const float* __restrict__ p2) {
    int chunk = blockIdx.x;               // 8 chunks of 128 outers
    int b = blockIdx.y;
    int i0 = threadIdx.x * 4;             // 256 threads * 4 cols = 1024
    size_t bb = (size_t)b * HWD * HWD;
    float m0 = -3.4e38f, m1 = -3.4e38f, m2 = -3.4e38f, m3 = -3.4e38f;
    int oBeg = chunk * 128, oEnd = oBeg + 128;
    if (p2) {
        for (int o = oBeg; o < oEnd; o++) {
            const float4 v = *(const float4*)(p1 + bb + (size_t)o * HWD + i0);
            const float4 w = *(const float4*)(p2 + bb + (size_t)o * HWD + i0);
            m0 = fmaxf(m0, v.x + w.x); m1 = fmaxf(m1, v.y + w.y);
            m2 = fmaxf(m2, v.z + w.z); m3 = fmaxf(m3, v.w + w.w);
        }
    } else {
        for (int o = oBeg; o < oEnd; o++) {
            const float4 v = *(const float4*)(p1 + bb + (size_t)o * HWD + i0);
            m0 = fmaxf(m0, v.x); m1 = fmaxf(m1, v.y);
            m2 = fmaxf(m2, v.z); m3 = fmaxf(m3, v.w);
        }
    }
    int ib = b * HWD + i0;
    atomicMax(&g_bmaxu[ib + 0], enc_f(m0));
    atomicMax(&g_bmaxu[ib + 1], enc_f(m1));
    atomicMax(&g_bmaxu[ib + 2], enc_f(m2));
    atomicMax(&g_bmaxu[ib + 3], enc_f(m3));
}

// ---------------- mutual matching #1: writes g_mm and g_mmT ----------------
__global__ void mm_kernel(const float* __restrict__ corr) {
    int to = blockIdx.x, ti = blockIdx.y;
    if (ti < to) return;                  // handle (to,ti) & (ti,to) together
    int b = blockIdx.z;
    size_t base = (size_t)b * HWD * HWD;
    __shared__ float s1[32][33], s2[32][33];
    int tx = threadIdx.x, ty0 = threadIdx.y;   // 32 x 8
    #pragma unroll
    for (int k = 0; k < 4; k++) {
        int y = ty0 + k * 8;
        int o1 = to * 32 + y, i1 = ti * 32 + tx;
        float c1 = corr[base + (size_t)o1 * HWD + i1];
        float v1 = c1 * c1 * c1 /
                   ((g_amax[b * HWD + o1] + EPSF) * (dec_f(g_bmaxu[b * HWD + i1]) + EPSF));
        g_mm[base + (size_t)o1 * HWD + i1] = v1;
        s1[y][tx] = v1;
        int o2 = ti * 32 + y, i2 = to * 32 + tx;
        float c2 = corr[base + (size_t)o2 * HWD + i2];
        float v2 = c2 * c2 * c2 /
                   ((g_amax[b * HWD + o2] + EPSF) * (dec_f(g_bmaxu[b * HWD + i2]) + EPSF));
        g_mm[base + (size_t)o2 * HWD + i2] = v2;
        s2[y][tx] = v2;
    }
    __syncthreads();
    #pragma unroll
    for (int k = 0; k < 4; k++) {
        int y = ty0 + k * 8;
        g_mmT[base + (size_t)(to * 32 + y) * HWD + ti * 32 + tx] = s2[tx][y];
        g_mmT[base + (size_t)(ti * 32 + y) * HWD + to * 32 + tx] = s1[tx][y];
    }
}

// ---------------- 3x3 conv over contiguous inner 32x32, SAME zero pad ----------------
// in: [Bb, Ci, HWD(outer), HWD(inner)], out: [Bb, Co, HWD, HWD]
template <int Ci, int Co>
__global__ void __launch_bounds__(128) conv_inner_kernel(
    const float* __restrict__ in, const float* __restrict__ w,
    const float* __restrict__ bias, float* __restrict__ out) {
    extern __shared__ float sm[];
    float* tile = sm;                        // Ci * 34*34
    float* wsm  = sm + Ci * 1156;            // Co*Ci*9
    float* bsm  = wsm + Co * Ci * 9;         // Co
    int blk = blockIdx.x;
    int b = blk >> 10;
    int o = blk & 1023;
    int tid = threadIdx.x;
    for (int idx = tid; idx < Co * Ci * 9; idx += 128) wsm[idx] = w[idx];
    if (tid < Co) bsm[tid] = bias[tid];
    size_t inBase = (size_t)b * Ci * HWD * HWD + (size_t)o * HWD;
    for (int idx = tid; idx < Ci * 1156; idx += 128) {
        int ci = idx / 1156; int rem = idx - ci * 1156;
        int y = rem / 34, x = rem - y * 34;
        int gy = y - 1, gx = x - 1;
        float v = 0.f;
        if ((unsigned)gy < 32u && (unsigned)gx < 32u)
            v = in[inBase + (size_t)ci * HWD * HWD + gy * 32 + gx];
        tile[idx] = v;
    }
    __syncthreads();
    int py = tid >> 2;
    int px0 = (tid & 3) * 8;
    float acc[Co][8];
    #pragma unroll
    for (int co = 0; co < Co; co++)
        #pragma unroll
        for (int r = 0; r < 8; r++) acc[co][r] = 0.f;
    for (int ci = 0; ci < Ci; ci++) {
        const float* tc = tile + ci * 1156;
        #pragma unroll
        for (int dy = 0; dy < 3; dy++) {
            const float* row = tc + (py + dy) * 34 + px0;
            float t[10];
            #pragma unroll
            for (int j = 0; j < 10; j++) t[j] = row[j];
            #pragma unroll
            for (int dx = 0; dx < 3; dx++) {
                #pragma unroll
                for (int co = 0; co < Co; co++) {
                    float wv = wsm[(co * Ci + ci) * 9 + dy * 3 + dx];
                    #pragma unroll
                    for (int r = 0; r < 8; r++)
                        acc[co][r] = fmaf(t[dx + r], wv, acc[co][r]);
                }
            }
        }
    }
    size_t ob = (size_t)b * Co * HWD * HWD + (size_t)o * HWD + py * 32 + px0;
    #pragma unroll
    for (int co = 0; co < Co; co++) {
        float bv = bsm[co];
        #pragma unroll
        for (int r = 0; r < 8; r++)
            out[ob + (size_t)co * HWD * HWD + r] = acc[co][r] + bv;
    }
}

// ---------------- fused combine: next = relu(a + bT), nextT = relu(aT + b) -------
template <int Co, bool WN, bool WNT>
__global__ void combine_kernel(const float* __restrict__ A, const float* __restrict__ Bm,
                               float* __restrict__ N, float* __restrict__ NT) {
    int to = blockIdx.x, ti = blockIdx.y;
    if (ti < to) return;
    int bc = blockIdx.z;
    size_t base = (size_t)bc * HWD * HWD;
    __shared__ float sA1[32][33], sA2[32][33], sB1[32][33], sB2[32][33];
    int tx = threadIdx.x, ty0 = threadIdx.y;
    #pragma unroll
    for (int k = 0; k < 4; k++) {
        int y = ty0 + k * 8;
        size_t i1 = base + (size_t)(to * 32 + y) * HWD + ti * 32 + tx;
        size_t i2 = base + (size_t)(ti * 32 + y) * HWD + to * 32 + tx;
        sA1[y][tx] = A[i1];  sA2[y][tx] = A[i2];
        sB1[y][tx] = Bm[i1]; sB2[y][tx] = Bm[i2];
    }
    __syncthreads();
    #pragma unroll
    for (int k = 0; k < 4; k++) {
        int y = ty0 + k * 8;
        size_t i1 = base + (size_t)(to * 32 + y) * HWD + ti * 32 + tx;
        size_t i2 = base + (size_t)(ti * 32 + y) * HWD + to * 32 + tx;
        if (WN) {
            N[i1] = fmaxf(sA1[y][tx] + sB2[tx][y], 0.f);
            N[i2] = fmaxf(sA2[y][tx] + sB1[tx][y], 0.f);
        }
        if (WNT) {
            NT[i1] = fmaxf(sA2[tx][y] + sB1[y][tx], 0.f);
            NT[i2] = fmaxf(sA1[tx][y] + sB2[y][tx], 0.f);
        }
    }
}

// ---------------- mutual matching #2 + mask + softmax -> g_attn ----------------
__global__ void softmax_kernel(const int* __restrict__ mask) {
    int row = blockIdx.x;                 // b*HWD + o
    int b = row >> 10;
    size_t base = (size_t)row * HWD;
    __shared__ float vals[1024];
    __shared__ float red[256];
    int tid = threadIdx.x;
    float am = g_amax[row] + EPSF;
    float lm = -3.4e38f;
    for (int j = tid; j < HWD; j += 256) {
        float c = g_y1[base + j] + g_z[base + j];
        float bm = dec_f(g_bmaxu[(b << 10) + j]) + EPSF;
        float v = c * c * c / (am * bm);
        if (mask[(b << 10) + j] != 0) v = 1e-4f;
        v *= 3.0f;
        vals[j] = v;
        lm = fmaxf(lm, v);
    }
    red[tid] = lm; __syncthreads();
    for (int s = 128; s > 0; s >>= 1) {
        if (tid < s) red[tid] = fmaxf(red[tid], red[tid + s]);
        __syncthreads();
    }
    float m = red[0];
    __syncthreads();
    float ls = 0.f;
    for (int j = tid; j < HWD; j += 256) {
        float e = __expf(vals[j] - m);
        vals[j] = e;
        ls += e;
    }
    red[tid] = ls; __syncthreads();
    for (int s = 128; s > 0; s >>= 1) {
        if (tid < s) red[tid] += red[tid + s];
        __syncthreads();
    }
    float inv = 1.f / red[0];
    __syncthreads();
    for (int j = tid; j < HWD; j += 256)
        g_attn[base + j] = vals[j] * inv;
}

// ---------------- out[b,c,q] = sum_k v[b,c,k] * attn[b,q,k] ----------------
__global__ void __launch_bounds__(256) gemm_kernel(const float* __restrict__ v,
                                                   float* __restrict__ out) {
    __shared__ __align__(16) float Vs[16][68];
    __shared__ __align__(16) float As[16][68];
    int b = blockIdx.z;
    int cT = blockIdx.x * 64;
    int qT = blockIdx.y * 64;
    int tid = threadIdx.x;
    int tx = tid & 15, ty = tid >> 4;
    float acc[4][4];
    #pragma unroll
    for (int i = 0; i < 4; i++)
        #pragma unroll
        for (int j = 0; j < 4; j++) acc[i][j] = 0.f;
    const float* vb = v + (size_t)b * 256 * 1024;
    const float* ab = g_attn + (size_t)b * HWD * HWD;
    for (int k0 = 0; k0 < 1024; k0 += 16) {
        #pragma unroll
        for (int i = 0; i < 4; i++) {
            int idx = tid + i * 256;
            int kk = idx & 15, cc = idx >> 4;
            Vs[kk][cc] = vb[(size_t)(cT + cc) * 1024 + k0 + kk];
            As[kk][cc] = ab[(size_t)(qT + cc) * HWD + k0 + kk];
        }
        __syncthreads();
        #pragma unroll
        for (int kk = 0; kk < 16; kk++) {
            float4 a4 = *(const float4*)&Vs[kk][ty * 4];
            float4 b4 = *(const float4*)&As[kk][tx * 4];
            float a[4] = {a4.x, a4.y, a4.z, a4.w};
            float c[4] = {b4.x, b4.y, b4.z, b4.w};
            #pragma unroll
            for (int i = 0; i < 4; i++)
                #pragma unroll
                for (int j = 0; j < 4; j++)
                    acc[i][j] = fmaf(a[i], c[j], acc[i][j]);
        }
        __syncthreads();
    }
    #pragma unroll
    for (int i = 0; i < 4; i++)
        #pragma unroll
        for (int j = 0; j < 4; j++)
            out[(size_t)(b * 256 + cT + ty * 4 + i) * 1024 + qT + tx * 4 + j] = acc[i][j];
}

// ---------------- host launch ----------------
extern "C" void kernel_launch(void* const* d_in, const int* in_sizes, int n_in,
                              void* d_out, int out_size) {
    const float* corr = (const float*)d_in[0];
    const float* v    = (const float*)d_in[1];
    const int*   mask = (const int*)d_in[2];
    const float* wq[3] = {(const float*)d_in[3],  (const float*)d_in[7],  (const float*)d_in[11]};
    const float* bq[3] = {(const float*)d_in[4],  (const float*)d_in[8],  (const float*)d_in[12]};
    const float* ws[3] = {(const float*)d_in[5],  (const float*)d_in[9],  (const float*)d_in[13]};
    const float* bs[3] = {(const float*)d_in[6],  (const float*)d_in[10], (const float*)d_in[14]};
    float* out = (float*)d_out;

    float *p_mm, *p_mmT, *p_P, *p_PT, *p_A, *p_B, *p_y1, *p_z, *p_amax;
    cudaGetSymbolAddress((void**)&p_mm,  g_mm);
    cudaGetSymbolAddress((void**)&p_mmT, g_mmT);
    cudaGetSymbolAddress((void**)&p_P,   g_P);
    cudaGetSymbolAddress((void**)&p_PT,  g_PT);
    cudaGetSymbolAddress((void**)&p_A,   g_A);
    cudaGetSymbolAddress((void**)&p_B,   g_Bf);
    cudaGetSymbolAddress((void**)&p_y1,  g_y1);
    cudaGetSymbolAddress((void**)&p_z,   g_z);
    cudaGetSymbolAddress((void**)&p_amax, g_amax);

    cudaFuncSetAttribute(conv_inner_kernel<1, 10>,  cudaFuncAttributeMaxDynamicSharedMemorySize, 51200);
    cudaFuncSetAttribute(conv_inner_kernel<10, 10>, cudaFuncAttributeMaxDynamicSharedMemorySize, 51200);
    cudaFuncSetAttribute(conv_inner_kernel<10, 1>,  cudaFuncAttributeMaxDynamicSharedMemorySize, 51200);
    const int sm110 = (1 * 1156 + 10 * 1 * 9 + 10) * 4;
    const int sm1010 = (10 * 1156 + 10 * 10 * 9 + 10) * 4;
    const int sm101 = (10 * 1156 + 1 * 10 * 9 + 1) * 4;

    dim3 tile32(32, 8);
    dim3 gridTiles(32, 32, Bb);

    // ---- mutual matching #1 ----
    initb_kernel<<<16, 256>>>();
    rowmax_kernel<<<Bb * HWD, 256>>>(corr, nullptr, p_amax);
    colmax_kernel<<<dim3(8, Bb), 256>>>(corr, nullptr);
    mm_kernel<<<gridTiles, tile32>>>(corr);

    // ---- stack A: (cur, curT) = (mm, mmT) ----
    conv_inner_kernel<1, 10><<<Bb * HWD, 128, sm110>>>(p_mm,  ws[0], bs[0], p_A);
    conv_inner_kernel<1, 10><<<Bb * HWD, 128, sm110>>>(p_mmT, wq[0], bq[0], p_B);
    combine_kernel<10, true, true><<<dim3(32, 32, Bb * 10), tile32>>>(p_A, p_B, p_P, p_PT);
    conv_inner_kernel<10, 10><<<Bb * HWD, 128, sm1010>>>(p_P,  ws[1], bs[1], p_A);
    conv_inner_kernel<10, 10><<<Bb * HWD, 128, sm1010>>>(p_PT, wq[1], bq[1], p_B);
    combine_kernel<10, true, true><<<dim3(32, 32, Bb * 10), tile32>>>(p_A, p_B, p_P, p_PT);
    conv_inner_kernel<10, 1><<<Bb * HWD, 128, sm101>>>(p_P,  ws[2], bs[2], p_A);
    conv_inner_kernel<10, 1><<<Bb * HWD, 128, sm101>>>(p_PT, wq[2], bq[2], p_B);
    combine_kernel<1, true, false><<<dim3(32, 32, Bb), tile32>>>(p_A, p_B, p_y1, nullptr);

    // ---- stack B: (cur, curT) = (mmT, mm); final result is curT = y2 ----
    conv_inner_kernel<1, 10><<<Bb * HWD, 128, sm110>>>(p_mmT, ws[0], bs[0], p_A);
    conv_inner_kernel<1, 10><<<Bb * HWD, 128, sm110>>>(p_mm,  wq[0], bq[0], p_B);
    combine_kernel<10, true, true><<<dim3(32, 32, Bb * 10), tile32>>>(p_A, p_B, p_P, p_PT);
    conv_inner_kernel<10, 10><<<Bb * HWD, 128, sm1010>>>(p_P,  ws[1], bs[1], p_A);
    conv_inner_kernel<10, 10><<<Bb * HWD, 128, sm1010>>>(p_PT, wq[1], bq[1], p_B);
    combine_kernel<10, true, true><<<dim3(32, 32, Bb * 10), tile32>>>(p_A, p_B, p_P, p_PT);
    conv_inner_kernel<10, 1><<<Bb * HWD, 128, sm101>>>(p_P,  ws[2], bs[2], p_A);
    conv_inner_kernel<10, 1><<<Bb * HWD, 128, sm101>>>(p_PT, wq[2], bq[2], p_B);
    combine_kernel<1, false, true><<<dim3(32, 32, Bb), tile32>>>(p_A, p_B, nullptr, p_z);

    // ---- mutual matching #2 (on cf = y1 + z, computed on the fly) + softmax ----
    rowmax_kernel<<<Bb * HWD, 256>>>(p_y1, p_z, p_amax);
    initb_kernel<<<16, 256>>>();
    colmax_kernel<<<dim3(8, Bb), 256>>>(p_y1, p_z);
    softmax_kernel<<<Bb * HWD, 256>>>(mask);

    // ---- weighted sum: out = v @ attn^T ----
    gemm_kernel<<<dim3(4, 16, Bb), 256>>>(v, out);
}

// round 3
// speedup vs baseline: 1.6157x; 1.6157x over previous
#include <cuda_runtime.h>
#include <cuda_bf16.h>
#include <cstdint>

#define Bb 4
#define HWD 1024   // 32*32 flattened outer (and inner) spatial dims
#define EPSF 1e-5f

typedef unsigned long long ull;

// ---------------- scratch (device globals; no allocation allowed) ----------------
__device__ float g_mm  [(size_t)Bb*HWD*HWD];
__device__ float g_mmT [(size_t)Bb*HWD*HWD];
__device__ float g_P   [(size_t)Bb*10*HWD*HWD];
__device__ float g_Q   [(size_t)Bb*10*HWD*HWD];
__device__ float g_y1  [(size_t)Bb*HWD*HWD];
__device__ float g_zT  [(size_t)Bb*HWD*HWD];
__device__ float g_cf  [(size_t)Bb*HWD*HWD];
__device__ float g_attn[(size_t)Bb*HWD*HWD];
__device__ float    g_amax [Bb*HWD];
__device__ unsigned g_bmaxu[Bb*HWD];

// ---------------- helpers ----------------
__device__ __forceinline__ unsigned enc_f(float f) {
    unsigned u = __float_as_uint(f);
    return (u & 0x80000000u) ? ~u : (u | 0x80000000u);
}
__device__ __forceinline__ float dec_f(unsigned u) {
    return __uint_as_float((u & 0x80000000u) ? (u & 0x7fffffffu) : ~u);
}

#define PACK2(p, lo, hi)  asm("mov.b64 %0, {%1, %2};" : "=l"(p) : "f"(lo), "f"(hi))
#define UNPACK2(lo, hi, p) asm("mov.b64 {%0, %1}, %2;" : "=f"(lo), "=f"(hi) : "l"(p))
#define FMA2(d, a, w)     asm("fma.rn.f32x2 %0, %1, %2, %3;" : "=l"(d) : "l"(a), "l"(w), "l"(d))

// ---------------- max reductions ----------------
__global__ void initb_kernel() {
    int i = blockIdx.x * blockDim.x + threadIdx.x;
    if (i < Bb * HWD) g_bmaxu[i] = 0u;
}

__global__ void rowmax_kernel(const float* __restrict__ p1, float* __restrict__ om) {
    int row = blockIdx.x;                 // b*HWD + o
    size_t base = (size_t)row * HWD;
    int tid = threadIdx.x;
    float m = -3.4e38f;
    for (int j = tid; j < HWD; j += 256) m = fmaxf(m, p1[base + j]);
    __shared__ float red[256];
    red[tid] = m; __syncthreads();
    for (int s = 128; s > 0; s >>= 1) {
        if (tid < s) red[tid] = fmaxf(red[tid], red[tid + s]);
        __syncthreads();
    }
    if (tid == 0) om[row] = red[0];
}

__global__ void colmax_kernel(const float* __restrict__ p1) {
    int chunk = blockIdx.x;               // 8 chunks of 128 outers
    int b = blockIdx.y;
    int i0 = threadIdx.x * 4;             // 256 threads * 4 cols = 1024
    size_t bb = (size_t)b * HWD * HWD;
    float m0 = -3.4e38f, m1 = -3.4e38f, m2 = -3.4e38f, m3 = -3.4e38f;
    int oBeg = chunk * 128, oEnd = oBeg + 128;
    for (int o = oBeg; o < oEnd; o++) {
        const float4 v = *(const float4*)(p1 + bb + (size_t)o * HWD + i0);
        m0 = fmaxf(m0, v.x); m1 = fmaxf(m1, v.y);
        m2 = fmaxf(m2, v.z); m3 = fmaxf(m3, v.w);
    }
    int ib = b * HWD + i0;
    atomicMax(&g_bmaxu[ib + 0], enc_f(m0));
    atomicMax(&g_bmaxu[ib + 1], enc_f(m1));
    atomicMax(&g_bmaxu[ib + 2], enc_f(m2));
    atomicMax(&g_bmaxu[ib + 3], enc_f(m3));
}

// ---------------- mutual matching #1: writes g_mm and g_mmT ----------------
__global__ void mm_kernel(const float* __restrict__ corr) {
    int to = blockIdx.x, ti = blockIdx.y;
    if (ti < to) return;                  // handle (to,ti) & (ti,to) together
    int b = blockIdx.z;
    size_t base = (size_t)b * HWD * HWD;
    __shared__ float s1[32][33], s2[32][33];
    int tx = threadIdx.x, ty0 = threadIdx.y;   // 32 x 8
    #pragma unroll
    for (int k = 0; k < 4; k++) {
        int y = ty0 + k * 8;
        int o1 = to * 32 + y, i1 = ti * 32 + tx;
        float c1 = corr[base + (size_t)o1 * HWD + i1];
        float v1 = c1 * c1 * c1 /
                   ((g_amax[b * HWD + o1] + EPSF) * (dec_f(g_bmaxu[b * HWD + i1]) + EPSF));
        g_mm[base + (size_t)o1 * HWD + i1] = v1;
        s1[y][tx] = v1;
        int o2 = ti * 32 + y, i2 = to * 32 + tx;
        float c2 = corr[base + (size_t)o2 * HWD + i2];
        float v2 = c2 * c2 * c2 /
                   ((g_amax[b * HWD + o2] + EPSF) * (dec_f(g_bmaxu[b * HWD + i2]) + EPSF));
        g_mm[base + (size_t)o2 * HWD + i2] = v2;
        s2[y][tx] = v2;
    }
    __syncthreads();
    #pragma unroll
    for (int k = 0; k < 4; k++) {
        int y = ty0 + k * 8;
        g_mmT[base + (size_t)(to * 32 + y) * HWD + ti * 32 + tx] = s2[tx][y];
        g_mmT[base + (size_t)(ti * 32 + y) * HWD + to * 32 + tx] = s1[tx][y];
    }
}

// ---------------- fused CenterPivotConv4d layer ----------------
// out[co][o][i] = relu( conv3x3_inner(in; wsp) + conv3x3_outer(in; wq) + bq+bsp )
// Block handles W consecutive outer columns (same outer row h) x full inner 32x32.
// smem: duplicated-pair weights (for f32x2) + 3*(W+2) inner-slices of the input.
template <int Ci, int Co, int W>
__global__ void __launch_bounds__(128, 3) fconv_kernel(
    const float* __restrict__ in,
    const float* __restrict__ wq, const float* __restrict__ bq,
    const float* __restrict__ wsp, const float* __restrict__ bsp,
    float* __restrict__ out)
{
    constexpr int R = 3 * (W + 2);
    constexpr int NW = Ci * 9 * Co;
    extern __shared__ unsigned char smraw[];
    ull*   wq2  = (ull*)smraw;               // [Ci*9*Co] duplicated pairs {w,w}
    ull*   ws2  = wq2 + NW;
    float* bsum = (float*)(ws2 + NW);        // [Co] (padded to 4)
    float* rows = bsum + ((Co + 3) & ~3);    // [R][1024]

    int tid = threadIdx.x;

    // stage weights (duplicated into both f32x2 halves) and summed bias
    for (int idx = tid; idx < NW; idx += 128) {
        int co = idx % Co; int r2 = idx / Co; int tap = r2 % 9; int ci = r2 / 9;
        float a = wq [(co * Ci + ci) * 9 + tap];
        float c = wsp[(co * Ci + ci) * 9 + tap];
        ull pa, pc; PACK2(pa, a, a); PACK2(pc, c, c);
        wq2[idx] = pa; ws2[idx] = pc;
    }
    if (tid < Co) bsum[tid] = bq[tid] + bsp[tid];

    constexpr int BPB = 1024 / W;
    int blk = blockIdx.x;
    int b   = blk / BPB;
    int rem = blk - b * BPB;
    int h   = rem / (32 / W);
    int w0  = (rem - h * (32 / W)) * W;

    int py  = tid >> 2;
    int px0 = (tid & 3) * 8;

    ull acc[Co][W][4];
    #pragma unroll
    for (int co = 0; co < Co; co++)
        #pragma unroll
        for (int c = 0; c < W; c++)
            #pragma unroll
            for (int rp = 0; rp < 4; rp++) acc[co][c][rp] = 0ull;

    for (int ci = 0; ci < Ci; ci++) {
        __syncthreads();
        // stage R inner-slices for this ci (zero-fill out-of-range outer neighbors)
        size_t cBase = ((size_t)(b * Ci + ci)) << 20;
        for (int idx = tid; idx < R * 256; idx += 128) {
            int k = idx >> 8; int j = idx & 255;
            int ry = k / (W + 2); int rx = k - ry * (W + 2);
            int ny = h - 1 + ry, nx = w0 - 1 + rx;
            float4 v = make_float4(0.f, 0.f, 0.f, 0.f);
            if ((unsigned)ny < 32u && (unsigned)nx < 32u)
                v = *(const float4*)(in + cBase + ((size_t)(ny * 32 + nx) << 10) + (j << 2));
            *(float4*)(rows + (k << 10) + (j << 2)) = v;
        }
        __syncthreads();

        #pragma unroll
        for (int c = 0; c < W; c++) {
            // ---- inner 3x3 conv (support dims), center slice for this output col ----
            const float* cr0 = rows + (((W + 2) + (c + 1)) << 10);
            #pragma unroll
            for (int dy = 0; dy < 3; dy++) {
                int iy = py + dy - 1;
                bool rowok = (unsigned)iy < 32u;
                const float* cr = cr0 + iy * 32;
                float t[10];
                #pragma unroll
                for (int j = 0; j < 10; j++) {
                    int x = px0 - 1 + j;
                    t[j] = (rowok && (unsigned)x < 32u) ? cr[x] : 0.f;
                }
                ull pr[9];
                #pragma unroll
                for (int i = 0; i < 9; i++) PACK2(pr[i], t[i], t[i + 1]);
                #pragma unroll
                for (int dx = 0; dx < 3; dx++) {
                    #pragma unroll
                    for (int co = 0; co < Co; co++) {
                        ull wv = ws2[(ci * 9 + dy * 3 + dx) * Co + co];
                        #pragma unroll
                        for (int rp = 0; rp < 4; rp++)
                            FMA2(acc[co][c][rp], pr[dx + 2 * rp], wv);
                    }
                }
            }
            // ---- outer 3x3 conv (query dims): same inner pixel from 9 slices ----
            #pragma unroll
            for (int ky = 0; ky < 3; ky++) {
                #pragma unroll
                for (int kx = 0; kx < 3; kx++) {
                    const ull* up = (const ull*)(rows + ((ky * (W + 2) + c + kx) << 10)
                                                 + py * 32 + px0);
                    ull u0 = up[0], u1 = up[1], u2 = up[2], u3 = up[3];
                    #pragma unroll
                    for (int co = 0; co < Co; co++) {
                        ull wv = wq2[(ci * 9 + ky * 3 + kx) * Co + co];
                        FMA2(acc[co][c][0], u0, wv);
                        FMA2(acc[co][c][1], u1, wv);
                        FMA2(acc[co][c][2], u2, wv);
                        FMA2(acc[co][c][3], u3, wv);
                    }
                }
            }
        }
    }

    // ---- epilogue: bias + relu, vectorized store ----
    #pragma unroll
    for (int co = 0; co < Co; co++) {
        float bsc = bsum[co];
        #pragma unroll
        for (int c = 0; c < W; c++) {
            float o8[8];
            #pragma unroll
            for (int rp = 0; rp < 4; rp++) {
                float lo, hi; UNPACK2(lo, hi, acc[co][c][rp]);
                o8[2 * rp]     = fmaxf(lo + bsc, 0.f);
                o8[2 * rp + 1] = fmaxf(hi + bsc, 0.f);
            }
            float4* op = (float4*)(out + (((size_t)(b * Co + co)) << 20)
                                   + ((size_t)(h * 32 + w0 + c) << 10) + py * 32 + px0);
            op[0] = make_float4(o8[0], o8[1], o8[2], o8[3]);
            op[1] = make_float4(o8[4], o8[5], o8[6], o8[7]);
        }
    }
}

// ---------------- cf = y1 + transpose(zT) ----------------
__global__ void transadd_kernel(const float* __restrict__ y1, const float* __restrict__ zT,
                                float* __restrict__ cf) {
    int to = blockIdx.x, ti = blockIdx.y, b = blockIdx.z;
    size_t base = (size_t)b << 20;
    __shared__ float s[32][33];
    int tx = threadIdx.x, ty0 = threadIdx.y;
    #pragma unroll
    for (int k = 0; k < 4; k++) {
        int y = ty0 + k * 8;
        s[y][tx] = zT[base + ((size_t)(ti * 32 + y) << 10) + to * 32 + tx];
    }
    __syncthreads();
    #pragma unroll
    for (int k = 0; k < 4; k++) {
        int y = ty0 + k * 8;
        size_t idx = base + ((size_t)(to * 32 + y) << 10) + ti * 32 + tx;
        cf[idx] = y1[idx] + s[tx][y];
    }
}

// ---------------- mutual matching #2 + mask + softmax -> g_attn ----------------
__global__ void softmax_kernel(const float* __restrict__ cf, const int* __restrict__ mask) {
    int row = blockIdx.x;                 // b*HWD + o
    int b = row >> 10;
    size_t base = (size_t)row * HWD;
    __shared__ float vals[1024];
    __shared__ float red[256];
    int tid = threadIdx.x;
    float am = g_amax[row] + EPSF;
    float lm = -3.4e38f;
    for (int j = tid; j < HWD; j += 256) {
        float c = cf[base + j];
        float bm = dec_f(g_bmaxu[(b << 10) + j]) + EPSF;
        float v = c * c * c / (am * bm);
        if (mask[(b << 10) + j] != 0) v = 1e-4f;
        v *= 3.0f;
        vals[j] = v;
        lm = fmaxf(lm, v);
    }
    red[tid] = lm; __syncthreads();
    for (int s = 128; s > 0; s >>= 1) {
        if (tid < s) red[tid] = fmaxf(red[tid], red[tid + s]);
        __syncthreads();
    }
    float m = red[0];
    __syncthreads();
    float ls = 0.f;
    for (int j = tid; j < HWD; j += 256) {
        float e = __expf(vals[j] - m);
        vals[j] = e;
        ls += e;
    }
    red[tid] = ls; __syncthreads();
    for (int s = 128; s > 0; s >>= 1) {
        if (tid < s) red[tid] += red[tid + s];
        __syncthreads();
    }
    float inv = 1.f / red[0];
    __syncthreads();
    for (int j = tid; j < HWD; j += 256)
        g_attn[base + j] = vals[j] * inv;
}

// ---------------- out[b,c,q] = sum_k v[b,c,k] * attn[b,q,k] ----------------
__global__ void __launch_bounds__(256) gemm_kernel(const float* __restrict__ v,
                                                   float* __restrict__ out) {
    __shared__ __align__(16) float Vs[16][68];
    __shared__ __align__(16) float As[16][68];
    int b = blockIdx.z;
    int cT = blockIdx.x * 64;
    int qT = blockIdx.y * 64;
    int tid = threadIdx.x;
    int tx = tid & 15, ty = tid >> 4;
    float acc[4][4];
    #pragma unroll
    for (int i = 0; i < 4; i++)
        #pragma unroll
        for (int j = 0; j < 4; j++) acc[i][j] = 0.f;
    const float* vb = v + (size_t)b * 256 * 1024;
    const float* ab = g_attn + (size_t)b * HWD * HWD;
    for (int k0 = 0; k0 < 1024; k0 += 16) {
        #pragma unroll
        for (int i = 0; i < 4; i++) {
            int idx = tid + i * 256;
            int kk = idx & 15, cc = idx >> 4;
            Vs[kk][cc] = vb[(size_t)(cT + cc) * 1024 + k0 + kk];
            As[kk][cc] = ab[(size_t)(qT + cc) * HWD + k0 + kk];
        }
        __syncthreads();
        #pragma unroll
        for (int kk = 0; kk < 16; kk++) {
            float4 a4 = *(const float4*)&Vs[kk][ty * 4];
            float4 b4 = *(const float4*)&As[kk][tx * 4];
            float a[4] = {a4.x, a4.y, a4.z, a4.w};
            float c[4] = {b4.x, b4.y, b4.z, b4.w};
            #pragma unroll
            for (int i = 0; i < 4; i++)
                #pragma unroll
                for (int j = 0; j < 4; j++)
                    acc[i][j] = fmaf(a[i], c[j], acc[i][j]);
        }
        __syncthreads();
    }
    #pragma unroll
    for (int i = 0; i < 4; i++)
        #pragma unroll
        for (int j = 0; j < 4; j++)
            out[(size_t)(b * 256 + cT + ty * 4 + i) * 1024 + qT + tx * 4 + j] = acc[i][j];
}

// ---------------- host launch ----------------
static inline int fconv_smem(int Ci, int Co, int W) {
    return 2 * Ci * 9 * Co * 8 + ((Co + 3) & ~3) * 4 + 3 * (W + 2) * 1024 * 4;
}

extern "C" void kernel_launch(void* const* d_in, const int* in_sizes, int n_in,
                              void* d_out, int out_size) {
    const float* corr = (const float*)d_in[0];
    const float* v    = (const float*)d_in[1];
    const int*   mask = (const int*)d_in[2];
    const float* wq[3] = {(const float*)d_in[3],  (const float*)d_in[7],  (const float*)d_in[11]};
    const float* bq[3] = {(const float*)d_in[4],  (const float*)d_in[8],  (const float*)d_in[12]};
    const float* ws[3] = {(const float*)d_in[5],  (const float*)d_in[9],  (const float*)d_in[13]};
    const float* bs[3] = {(const float*)d_in[6],  (const float*)d_in[10], (const float*)d_in[14]};
    float* out = (float*)d_out;

    float *p_mm, *p_mmT, *p_P, *p_Q, *p_y1, *p_zT, *p_cf, *p_amax;
    cudaGetSymbolAddress((void**)&p_mm,  g_mm);
    cudaGetSymbolAddress((void**)&p_mmT, g_mmT);
    cudaGetSymbolAddress((void**)&p_P,   g_P);
    cudaGetSymbolAddress((void**)&p_Q,   g_Q);
    cudaGetSymbolAddress((void**)&p_y1,  g_y1);
    cudaGetSymbolAddress((void**)&p_zT,  g_zT);
    cudaGetSymbolAddress((void**)&p_cf,  g_cf);
    cudaGetSymbolAddress((void**)&p_amax, g_amax);

    const int sm110  = fconv_smem(1, 10, 1);
    const int sm1010 = fconv_smem(10, 10, 1);
    const int sm101  = fconv_smem(10, 1, 4);
    cudaFuncSetAttribute(fconv_kernel<1, 10, 1>,  cudaFuncAttributeMaxDynamicSharedMemorySize, sm110);
    cudaFuncSetAttribute(fconv_kernel<10, 10, 1>, cudaFuncAttributeMaxDynamicSharedMemorySize, sm1010);
    cudaFuncSetAttribute(fconv_kernel<10, 1, 4>,  cudaFuncAttributeMaxDynamicSharedMemorySize, sm101);

    dim3 tile32(32, 8);
    dim3 gridTiles(32, 32, Bb);

    // ---- mutual matching #1 (produces mm and mmT) ----
    initb_kernel<<<16, 256>>>();
    rowmax_kernel<<<Bb * HWD, 256>>>(corr, p_amax);
    colmax_kernel<<<dim3(8, Bb), 256>>>(corr);
    mm_kernel<<<gridTiles, tile32>>>(corr);

    // ---- stack A (normal orientation) -> y1 ----
    fconv_kernel<1, 10, 1> <<<Bb * 1024, 128, sm110 >>>(p_mm, wq[0], bq[0], ws[0], bs[0], p_P);
    fconv_kernel<10, 10, 1><<<Bb * 1024, 128, sm1010>>>(p_P,  wq[1], bq[1], ws[1], bs[1], p_Q);
    fconv_kernel<10, 1, 4> <<<Bb * 256,  128, sm101 >>>(p_Q,  wq[2], bq[2], ws[2], bs[2], p_y1);

    // ---- stack B (transposed orientation, same weights/kernel) -> zT ----
    fconv_kernel<1, 10, 1> <<<Bb * 1024, 128, sm110 >>>(p_mmT, wq[0], bq[0], ws[0], bs[0], p_P);
    fconv_kernel<10, 10, 1><<<Bb * 1024, 128, sm1010>>>(p_P,   wq[1], bq[1], ws[1], bs[1], p_Q);
    fconv_kernel<10, 1, 4> <<<Bb * 256,  128, sm101 >>>(p_Q,   wq[2], bq[2], ws[2], bs[2], p_zT);

    // ---- cf = y1 + T(zT) ----
    transadd_kernel<<<gridTiles, tile32>>>(p_y1, p_zT, p_cf);

    // ---- mutual matching #2 + masked softmax ----
    rowmax_kernel<<<Bb * HWD, 256>>>(p_cf, p_amax);
    initb_kernel<<<16, 256>>>();
    colmax_kernel<<<dim3(8, Bb), 256>>>(p_cf);
    softmax_kernel<<<Bb * HWD, 256>>>(p_cf, mask);

    // ---- weighted sum: out = v @ attn^T ----
    gemm_kernel<<<dim3(4, 16, Bb), 256>>>(v, out);
}

// round 4
// speedup vs baseline: 1.7481x; 1.0819x over previous
#include <cuda_runtime.h>
#include <cuda_bf16.h>
#include <cstdint>

#define Bb 4
#define HWD 1024   // 32*32 flattened outer (and inner) spatial dims
#define EPSF 1e-5f

#define SSTR 34            // padded row stride (floats) inside a staged slice
#define SLICE (32 * SSTR)  // 1088 floats per staged 32x32 slice

typedef unsigned long long ull;

// ---------------- scratch (device globals; no allocation allowed) ----------------
__device__ float g_mm  [(size_t)Bb*HWD*HWD];
__device__ float g_mmT [(size_t)Bb*HWD*HWD];
__device__ float g_P   [(size_t)Bb*10*HWD*HWD];
__device__ float g_Q   [(size_t)Bb*10*HWD*HWD];
__device__ float g_y1  [(size_t)Bb*HWD*HWD];
__device__ float g_zT  [(size_t)Bb*HWD*HWD];
__device__ float g_cf  [(size_t)Bb*HWD*HWD];
__device__ float g_attn[(size_t)Bb*HWD*HWD];
__device__ float    g_amax [Bb*HWD];
__device__ unsigned g_bmaxu[Bb*HWD];

// ---------------- helpers ----------------
__device__ __forceinline__ unsigned enc_f(float f) {
    unsigned u = __float_as_uint(f);
    return (u & 0x80000000u) ? ~u : (u | 0x80000000u);
}
__device__ __forceinline__ float dec_f(unsigned u) {
    return __uint_as_float((u & 0x80000000u) ? (u & 0x7fffffffu) : ~u);
}

#define PACK2(p, lo, hi)  asm("mov.b64 %0, {%1, %2};" : "=l"(p) : "f"(lo), "f"(hi))
#define UNPACK2(lo, hi, p) asm("mov.b64 {%0, %1}, %2;" : "=f"(lo), "=f"(hi) : "l"(p))
#define FMA2(d, a, w)     asm("fma.rn.f32x2 %0, %1, %2, %3;" : "=l"(d) : "l"(a), "l"(w), "l"(d))

// ---------------- max reductions ----------------
__global__ void initb_kernel() {
    int i = blockIdx.x * blockDim.x + threadIdx.x;
    if (i < Bb * HWD) g_bmaxu[i] = 0u;
}

__global__ void rowmax_kernel(const float* __restrict__ p1, float* __restrict__ om) {
    int row = blockIdx.x;                 // b*HWD + o
    size_t base = (size_t)row * HWD;
    int tid = threadIdx.x;
    float m = -3.4e38f;
    for (int j = tid; j < HWD; j += 256) m = fmaxf(m, p1[base + j]);
    __shared__ float red[256];
    red[tid] = m; __syncthreads();
    for (int s = 128; s > 0; s >>= 1) {
        if (tid < s) red[tid] = fmaxf(red[tid], red[tid + s]);
        __syncthreads();
    }
    if (tid == 0) om[row] = red[0];
}

__global__ void colmax_kernel(const float* __restrict__ p1) {
    int chunk = blockIdx.x;               // 8 chunks of 128 outers
    int b = blockIdx.y;
    int i0 = threadIdx.x * 4;             // 256 threads * 4 cols = 1024
    size_t bb = (size_t)b * HWD * HWD;
    float m0 = -3.4e38f, m1 = -3.4e38f, m2 = -3.4e38f, m3 = -3.4e38f;
    int oBeg = chunk * 128, oEnd = oBeg + 128;
    for (int o = oBeg; o < oEnd; o++) {
        const float4 v = *(const float4*)(p1 + bb + (size_t)o * HWD + i0);
        m0 = fmaxf(m0, v.x); m1 = fmaxf(m1, v.y);
        m2 = fmaxf(m2, v.z); m3 = fmaxf(m3, v.w);
    }
    int ib = b * HWD + i0;
    atomicMax(&g_bmaxu[ib + 0], enc_f(m0));
    atomicMax(&g_bmaxu[ib + 1], enc_f(m1));
    atomicMax(&g_bmaxu[ib + 2], enc_f(m2));
    atomicMax(&g_bmaxu[ib + 3], enc_f(m3));
}

// ---------------- mutual matching #1: writes g_mm and g_mmT ----------------
__global__ void mm_kernel(const float* __restrict__ corr) {
    int to = blockIdx.x, ti = blockIdx.y;
    if (ti < to) return;                  // handle (to,ti) & (ti,to) together
    int b = blockIdx.z;
    size_t base = (size_t)b * HWD * HWD;
    __shared__ float s1[32][33], s2[32][33];
    int tx = threadIdx.x, ty0 = threadIdx.y;   // 32 x 8
    #pragma unroll
    for (int k = 0; k < 4; k++) {
        int y = ty0 + k * 8;
        int o1 = to * 32 + y, i1 = ti * 32 + tx;
        float c1 = corr[base + (size_t)o1 * HWD + i1];
        float v1 = c1 * c1 * c1 /
                   ((g_amax[b * HWD + o1] + EPSF) * (dec_f(g_bmaxu[b * HWD + i1]) + EPSF));
        g_mm[base + (size_t)o1 * HWD + i1] = v1;
        s1[y][tx] = v1;
        int o2 = ti * 32 + y, i2 = to * 32 + tx;
        float c2 = corr[base + (size_t)o2 * HWD + i2];
        float v2 = c2 * c2 * c2 /
                   ((g_amax[b * HWD + o2] + EPSF) * (dec_f(g_bmaxu[b * HWD + i2]) + EPSF));
        g_mm[base + (size_t)o2 * HWD + i2] = v2;
        s2[y][tx] = v2;
    }
    __syncthreads();
    #pragma unroll
    for (int k = 0; k < 4; k++) {
        int y = ty0 + k * 8;
        g_mmT[base + (size_t)(to * 32 + y) * HWD + ti * 32 + tx] = s2[tx][y];
        g_mmT[base + (size_t)(ti * 32 + y) * HWD + to * 32 + tx] = s1[tx][y];
    }
}

// ---------------- fused CenterPivotConv4d layer ----------------
// out[co][o][i] = relu( conv3x3_inner(in; wsp) + conv3x3_outer(in; wq) + bq+bsp )
// Block handles W consecutive outer columns (same outer row h) x full inner 32x32.
// smem: duplicated-pair weights (for f32x2) + 3*(W+2) inner-slices, row stride 34.
template <int Ci, int Co, int W>
__global__ void __launch_bounds__(128, 3) fconv_kernel(
    const float* __restrict__ in,
    const float* __restrict__ wq, const float* __restrict__ bq,
    const float* __restrict__ wsp, const float* __restrict__ bsp,
    float* __restrict__ out)
{
    constexpr int R = 3 * (W + 2);
    constexpr int NW = Ci * 9 * Co;
    extern __shared__ unsigned char smraw[];
    ull*   wq2  = (ull*)smraw;               // [Ci*9*Co] duplicated pairs {w,w}
    ull*   ws2  = wq2 + NW;
    float* bsum = (float*)(ws2 + NW);        // [Co] (padded to 4)
    float* rows = bsum + ((Co + 3) & ~3);    // [R][SLICE]

    int tid = threadIdx.x;

    // stage weights (duplicated into both f32x2 halves) and summed bias
    for (int idx = tid; idx < NW; idx += 128) {
        int co = idx % Co; int r2 = idx / Co; int tap = r2 % 9; int ci = r2 / 9;
        float a = wq [(co * Ci + ci) * 9 + tap];
        float c = wsp[(co * Ci + ci) * 9 + tap];
        ull pa, pc; PACK2(pa, a, a); PACK2(pc, c, c);
        wq2[idx] = pa; ws2[idx] = pc;
    }
    if (tid < Co) bsum[tid] = bq[tid] + bsp[tid];

    constexpr int BPB = 1024 / W;
    int blk = blockIdx.x;
    int b   = blk / BPB;
    int rem = blk - b * BPB;
    int h   = rem / (32 / W);
    int w0  = (rem - h * (32 / W)) * W;

    int py  = tid >> 2;
    int px0 = (tid & 3) * 8;

    ull acc[Co][W][4];
    #pragma unroll
    for (int co = 0; co < Co; co++)
        #pragma unroll
        for (int c = 0; c < W; c++)
            #pragma unroll
            for (int rp = 0; rp < 4; rp++) acc[co][c][rp] = 0ull;

    for (int ci = 0; ci < Ci; ci++) {
        __syncthreads();
        // stage R inner-slices for this ci (zero-fill out-of-range outer neighbors)
        size_t cBase = ((size_t)(b * Ci + ci)) << 20;
        for (int idx = tid; idx < R * 256; idx += 128) {
            int k = idx >> 8; int j = idx & 255;          // j: float4 index in slice
            int ry = k / (W + 2); int rx = k - ry * (W + 2);
            int ny = h - 1 + ry, nx = w0 - 1 + rx;
            float4 v = make_float4(0.f, 0.f, 0.f, 0.f);
            if ((unsigned)ny < 32u && (unsigned)nx < 32u)
                v = *(const float4*)(in + cBase + ((size_t)(ny * 32 + nx) << 10) + (j << 2));
            int irow = j >> 3, icol = (j & 7) << 2;
            ull* dst = (ull*)(rows + k * SLICE + irow * SSTR + icol);
            ull p0, p1; PACK2(p0, v.x, v.y); PACK2(p1, v.z, v.w);
            dst[0] = p0; dst[1] = p1;
        }
        __syncthreads();

        #pragma unroll
        for (int c = 0; c < W; c++) {
            // ---- inner 3x3 conv (support dims), center slice for this output col ----
            const float* cr0 = rows + ((W + 2) + (c + 1)) * SLICE;
            #pragma unroll
            for (int dy = 0; dy < 3; dy++) {
                int iy = py + dy - 1;
                bool rowok = (unsigned)iy < 32u;
                const float* cr = cr0 + iy * SSTR;
                float t[10];
                #pragma unroll
                for (int j = 0; j < 10; j++) {
                    int x = px0 - 1 + j;
                    t[j] = (rowok && (unsigned)x < 32u) ? cr[x] : 0.f;
                }
                ull pr[9];
                #pragma unroll
                for (int i = 0; i < 9; i++) PACK2(pr[i], t[i], t[i + 1]);
                #pragma unroll
                for (int dx = 0; dx < 3; dx++) {
                    #pragma unroll
                    for (int co = 0; co < Co; co++) {
                        ull wv = ws2[(ci * 9 + dy * 3 + dx) * Co + co];
                        #pragma unroll
                        for (int rp = 0; rp < 4; rp++)
                            FMA2(acc[co][c][rp], pr[dx + 2 * rp], wv);
                    }
                }
            }
            // ---- outer 3x3 conv (query dims): same inner pixel from 9 slices ----
            #pragma unroll
            for (int ky = 0; ky < 3; ky++) {
                #pragma unroll
                for (int kx = 0; kx < 3; kx++) {
                    const ull* up = (const ull*)(rows + (ky * (W + 2) + c + kx) * SLICE
                                                 + py * SSTR + px0);
                    ull u0 = up[0], u1 = up[1], u2 = up[2], u3 = up[3];
                    #pragma unroll
                    for (int co = 0; co < Co; co++) {
                        ull wv = wq2[(ci * 9 + ky * 3 + kx) * Co + co];
                        FMA2(acc[co][c][0], u0, wv);
                        FMA2(acc[co][c][1], u1, wv);
                        FMA2(acc[co][c][2], u2, wv);
                        FMA2(acc[co][c][3], u3, wv);
                    }
                }
            }
        }
    }

    // ---- epilogue: bias + relu, vectorized store ----
    #pragma unroll
    for (int co = 0; co < Co; co++) {
        float bsc = bsum[co];
        #pragma unroll
        for (int c = 0; c < W; c++) {
            float o8[8];
            #pragma unroll
            for (int rp = 0; rp < 4; rp++) {
                float lo, hi; UNPACK2(lo, hi, acc[co][c][rp]);
                o8[2 * rp]     = fmaxf(lo + bsc, 0.f);
                o8[2 * rp + 1] = fmaxf(hi + bsc, 0.f);
            }
            float4* op = (float4*)(out + (((size_t)(b * Co + co)) << 20)
                                   + ((size_t)(h * 32 + w0 + c) << 10) + py * 32 + px0);
            op[0] = make_float4(o8[0], o8[1], o8[2], o8[3]);
            op[1] = make_float4(o8[4], o8[5], o8[6], o8[7]);
        }
    }
}

// ---------------- cf = y1 + transpose(zT) ----------------
__global__ void transadd_kernel(const float* __restrict__ y1, const float* __restrict__ zT,
                                float* __restrict__ cf) {
    int to = blockIdx.x, ti = blockIdx.y, b = blockIdx.z;
    size_t base = (size_t)b << 20;
    __shared__ float s[32][33];
    int tx = threadIdx.x, ty0 = threadIdx.y;
    #pragma unroll
    for (int k = 0; k < 4; k++) {
        int y = ty0 + k * 8;
        s[y][tx] = zT[base + ((size_t)(ti * 32 + y) << 10) + to * 32 + tx];
    }
    __syncthreads();
    #pragma unroll
    for (int k = 0; k < 4; k++) {
        int y = ty0 + k * 8;
        size_t idx = base + ((size_t)(to * 32 + y) << 10) + ti * 32 + tx;
        cf[idx] = y1[idx] + s[tx][y];
    }
}

// ---------------- mutual matching #2 + mask + softmax -> g_attn ----------------
__global__ void softmax_kernel(const float* __restrict__ cf, const int* __restrict__ mask) {
    int row = blockIdx.x;                 // b*HWD + o
    int b = row >> 10;
    size_t base = (size_t)row * HWD;
    __shared__ float vals[1024];
    __shared__ float red[256];
    int tid = threadIdx.x;
    float am = g_amax[row] + EPSF;
    float lm = -3.4e38f;
    for (int j = tid; j < HWD; j += 256) {
        float c = cf[base + j];
        float bm = dec_f(g_bmaxu[(b << 10) + j]) + EPSF;
        float v = c * c * c / (am * bm);
        if (mask[(b << 10) + j] != 0) v = 1e-4f;
        v *= 3.0f;
        vals[j] = v;
        lm = fmaxf(lm, v);
    }
    red[tid] = lm; __syncthreads();
    for (int s = 128; s > 0; s >>= 1) {
        if (tid < s) red[tid] = fmaxf(red[tid], red[tid + s]);
        __syncthreads();
    }
    float m = red[0];
    __syncthreads();
    float ls = 0.f;
    for (int j = tid; j < HWD; j += 256) {
        float e = __expf(vals[j] - m);
        vals[j] = e;
        ls += e;
    }
    red[tid] = ls; __syncthreads();
    for (int s = 128; s > 0; s >>= 1) {
        if (tid < s) red[tid] += red[tid + s];
        __syncthreads();
    }
    float inv = 1.f / red[0];
    __syncthreads();
    for (int j = tid; j < HWD; j += 256)
        g_attn[base + j] = vals[j] * inv;
}

// ---------------- out[b,c,q] = sum_k v[b,c,k] * attn[b,q,k] ----------------
__global__ void __launch_bounds__(256) gemm_kernel(const float* __restrict__ v,
                                                   float* __restrict__ out) {
    __shared__ __align__(16) float Vs[16][68];
    __shared__ __align__(16) float As[16][68];
    int b = blockIdx.z;
    int cT = blockIdx.x * 64;
    int qT = blockIdx.y * 64;
    int tid = threadIdx.x;
    int tx = tid & 15, ty = tid >> 4;
    ull acc2[4][2];
    #pragma unroll
    for (int i = 0; i < 4; i++) { acc2[i][0] = 0ull; acc2[i][1] = 0ull; }
    const float* vb = v + (size_t)b * 256 * 1024;
    const float* ab = g_attn + (size_t)b * HWD * HWD;
    for (int k0 = 0; k0 < 1024; k0 += 16) {
        #pragma unroll
        for (int i = 0; i < 4; i++) {
            int idx = tid + i * 256;
            int kk = idx & 15, cc = idx >> 4;
            Vs[kk][cc] = vb[(size_t)(cT + cc) * 1024 + k0 + kk];
            As[kk][cc] = ab[(size_t)(qT + cc) * HWD + k0 + kk];
        }
        __syncthreads();
        #pragma unroll
        for (int kk = 0; kk < 16; kk++) {
            float4 a4 = *(const float4*)&Vs[kk][ty * 4];
            const ull* bp = (const ull*)&As[kk][tx * 4];
            ull b0 = bp[0], b1 = bp[1];
            float a[4] = {a4.x, a4.y, a4.z, a4.w};
            #pragma unroll
            for (int i = 0; i < 4; i++) {
                ull ad; PACK2(ad, a[i], a[i]);
                FMA2(acc2[i][0], b0, ad);
                FMA2(acc2[i][1], b1, ad);
            }
        }
        __syncthreads();
    }
    #pragma unroll
    for (int i = 0; i < 4; i++) {
        float r0, r1, r2, r3;
        UNPACK2(r0, r1, acc2[i][0]);
        UNPACK2(r2, r3, acc2[i][1]);
        *(float4*)(out + (size_t)(b * 256 + cT + ty * 4 + i) * 1024 + qT + tx * 4)
            = make_float4(r0, r1, r2, r3);
    }
}

// ---------------- host launch ----------------
static inline int fconv_smem(int Ci, int Co, int W) {
    return 2 * Ci * 9 * Co * 8 + ((Co + 3) & ~3) * 4 + 3 * (W + 2) * SLICE * 4;
}

extern "C" void kernel_launch(void* const* d_in, const int* in_sizes, int n_in,
                              void* d_out, int out_size) {
    const float* corr = (const float*)d_in[0];
    const float* v    = (const float*)d_in[1];
    const int*   mask = (const int*)d_in[2];
    const float* wq[3] = {(const float*)d_in[3],  (const float*)d_in[7],  (const float*)d_in[11]};
    const float* bq[3] = {(const float*)d_in[4],  (const float*)d_in[8],  (const float*)d_in[12]};
    const float* ws[3] = {(const float*)d_in[5],  (const float*)d_in[9],  (const float*)d_in[13]};
    const float* bs[3] = {(const float*)d_in[6],  (const float*)d_in[10], (const float*)d_in[14]};
    float* out = (float*)d_out;

    float *p_mm, *p_mmT, *p_P, *p_Q, *p_y1, *p_zT, *p_cf, *p_amax;
    cudaGetSymbolAddress((void**)&p_mm,  g_mm);
    cudaGetSymbolAddress((void**)&p_mmT, g_mmT);
    cudaGetSymbolAddress((void**)&p_P,   g_P);
    cudaGetSymbolAddress((void**)&p_Q,   g_Q);
    cudaGetSymbolAddress((void**)&p_y1,  g_y1);
    cudaGetSymbolAddress((void**)&p_zT,  g_zT);
    cudaGetSymbolAddress((void**)&p_cf,  g_cf);
    cudaGetSymbolAddress((void**)&p_amax, g_amax);

    const int sm110  = fconv_smem(1, 10, 1);
    const int sm1010 = fconv_smem(10, 10, 1);
    const int sm101  = fconv_smem(10, 1, 4);
    cudaFuncSetAttribute(fconv_kernel<1, 10, 1>,  cudaFuncAttributeMaxDynamicSharedMemorySize, sm110);
    cudaFuncSetAttribute(fconv_kernel<10, 10, 1>, cudaFuncAttributeMaxDynamicSharedMemorySize, sm1010);
    cudaFuncSetAttribute(fconv_kernel<10, 1, 4>,  cudaFuncAttributeMaxDynamicSharedMemorySize, sm101);

    dim3 tile32(32, 8);
    dim3 gridTiles(32, 32, Bb);

    // ---- mutual matching #1 (produces mm and mmT) ----
    initb_kernel<<<16, 256>>>();
    rowmax_kernel<<<Bb * HWD, 256>>>(corr, p_amax);
    colmax_kernel<<<dim3(8, Bb), 256>>>(corr);
    mm_kernel<<<gridTiles, tile32>>>(corr);

    // ---- stack A (normal orientation) -> y1 ----
    fconv_kernel<1, 10, 1> <<<Bb * 1024, 128, sm110 >>>(p_mm, wq[0], bq[0], ws[0], bs[0], p_P);
    fconv_kernel<10, 10, 1><<<Bb * 1024, 128, sm1010>>>(p_P,  wq[1], bq[1], ws[1], bs[1], p_Q);
    fconv_kernel<10, 1, 4> <<<Bb * 256,  128, sm101 >>>(p_Q,  wq[2], bq[2], ws[2], bs[2], p_y1);

    // ---- stack B (transposed orientation, same weights/kernel) -> zT ----
    fconv_kernel<1, 10, 1> <<<Bb * 1024, 128, sm110 >>>(p_mmT, wq[0], bq[0], ws[0], bs[0], p_P);
    fconv_kernel<10, 10, 1><<<Bb * 1024, 128, sm1010>>>(p_P,   wq[1], bq[1], ws[1], bs[1], p_Q);
    fconv_kernel<10, 1, 4> <<<Bb * 256,  128, sm101 >>>(p_Q,   wq[2], bq[2], ws[2], bs[2], p_zT);

    // ---- cf = y1 + T(zT) ----
    transadd_kernel<<<gridTiles, tile32>>>(p_y1, p_zT, p_cf);

    // ---- mutual matching #2 + masked softmax ----
    rowmax_kernel<<<Bb * HWD, 256>>>(p_cf, p_amax);
    initb_kernel<<<16, 256>>>();
    colmax_kernel<<<dim3(8, Bb), 256>>>(p_cf);
    softmax_kernel<<<Bb * HWD, 256>>>(p_cf, mask);

    // ---- weighted sum: out = v @ attn^T ----
    gemm_kernel<<<dim3(4, 16, Bb), 256>>>(v, out);
}